// round 2
// baseline (speedup 1.0000x reference)
#include <cuda_runtime.h>
#include <cstdint>
#include <cstddef>

// Problem constants
#define BB 4
#define TT 2048
#define CC 1024
#define HH 16
#define DD 64
#define C3 (3 * CC)

// Scratch (allocation-free rule: __device__ globals)
__device__ float g_kqv[(size_t)BB * TT * C3];  // [B,T,3C]  (k | q | v)
__device__ float g_y[(size_t)BB * TT * CC];    // [B,T,C]

// ---------------------------------------------------------------------------
// SGEMM with bias: C[M,N] = A[M,K] @ B[K,N] + bias[N]
// Block tile 128x128, K-step 8, 256 threads, 8x8 per thread.
// Requires M%128==0, N%128==0, K%8==0 (true for all our shapes).
// ---------------------------------------------------------------------------
__global__ void __launch_bounds__(256) sgemm_bias(
    const float* __restrict__ A, const float* __restrict__ Bm,
    const float* __restrict__ bias, float* __restrict__ Cm,
    int M, int N, int K)
{
    __shared__ float As[8][128];
    __shared__ float Bs[8][128];

    const int tid = threadIdx.x;
    const int bm = blockIdx.y * 128;
    const int bn = blockIdx.x * 128;
    const int tx = tid & 15;       // 0..15 -> col group
    const int ty = tid >> 4;       // 0..15 -> row group

    const int arow = tid >> 1;           // 0..127
    const int acol = (tid & 1) << 2;     // 0 or 4
    const int brow = tid >> 5;           // 0..7
    const int bcol = (tid & 31) << 2;    // 0..124

    const float* Ap = A + (size_t)(bm + arow) * K + acol;
    const float* Bp = Bm + (size_t)brow * N + bn + bcol;

    float acc[8][8];
#pragma unroll
    for (int i = 0; i < 8; i++)
#pragma unroll
        for (int j = 0; j < 8; j++) acc[i][j] = 0.0f;

    for (int k0 = 0; k0 < K; k0 += 8) {
        float4 a = *(const float4*)Ap;  Ap += 8;
        float4 b = *(const float4*)Bp;  Bp += (size_t)8 * N;

        As[acol + 0][arow] = a.x;
        As[acol + 1][arow] = a.y;
        As[acol + 2][arow] = a.z;
        As[acol + 3][arow] = a.w;
        *(float4*)&Bs[brow][bcol] = b;
        __syncthreads();

#pragma unroll
        for (int kk = 0; kk < 8; kk++) {
            float ar[8], br[8];
            *(float4*)(ar)     = *(const float4*)&As[kk][ty * 8];
            *(float4*)(ar + 4) = *(const float4*)&As[kk][ty * 8 + 4];
            *(float4*)(br)     = *(const float4*)&Bs[kk][tx * 8];
            *(float4*)(br + 4) = *(const float4*)&Bs[kk][tx * 8 + 4];
#pragma unroll
            for (int i = 0; i < 8; i++)
#pragma unroll
                for (int j = 0; j < 8; j++)
                    acc[i][j] = fmaf(ar[i], br[j], acc[i][j]);
        }
        __syncthreads();
    }

#pragma unroll
    for (int i = 0; i < 8; i++) {
        const size_t row = (size_t)(bm + ty * 8 + i);
        float* Cp = Cm + row * N + bn + tx * 8;
        const float* bp = bias + bn + tx * 8;
#pragma unroll
        for (int j = 0; j < 8; j += 4) {
            float4 v;
            v.x = acc[i][j + 0] + bp[j + 0];
            v.y = acc[i][j + 1] + bp[j + 1];
            v.z = acc[i][j + 2] + bp[j + 2];
            v.w = acc[i][j + 3] + bp[j + 3];
            *(float4*)(Cp + j) = v;
        }
    }
}

// ---------------------------------------------------------------------------
// Flash attention (fp32, online softmax), BQ=64 queries x BK=32 keys per tile.
// kqv layout: [B,T,3C] with segments k(0), q(C), v(2C); head h -> cols h*D..h*D+63.
// Output y: [B,T,C].
// Grid: (T/64, H, B), 256 threads.
// Thread map: tr=tid/16 (4 rows each: tr*4+ri), tc=tid%16.
//   S tile 64x32: cols tc*2+{0,1};  O tile 64x64: cols tc*4+{0..3}.
// ---------------------------------------------------------------------------
#define BQ 64
#define BK 32

__global__ void __launch_bounds__(256) attn_kernel(
    const float* __restrict__ kqv, const int* __restrict__ padmask,
    float* __restrict__ y)
{
    __shared__ float Qs[BQ][DD + 1];
    __shared__ float Ks[BK][DD + 1];
    __shared__ float Vs[BK][DD + 1];
    __shared__ float Ps[BQ][BK + 1];
    __shared__ float red[BQ][17];
    __shared__ float m_s[BQ], l_s[BQ], alpha_s[BQ];
    __shared__ int   padv[BK];

    const int q0 = blockIdx.x * BQ;
    const int h  = blockIdx.y;
    const int b  = blockIdx.z;
    const int tid = threadIdx.x;
    const int tr = tid >> 4;
    const int tc = tid & 15;
    const float scale = 0.125f;  // 1/sqrt(64)

    const float* base = kqv + (size_t)b * TT * C3 + (size_t)h * DD;
    const float* qbase = base + CC;       // q segment
    const float* kbase = base;            // k segment
    const float* vbase = base + 2 * CC;   // v segment

    // Load Q tile
    for (int i = tid; i < BQ * (DD / 4); i += 256) {
        int r = i >> 4, c4 = (i & 15) << 2;
        float4 v = *(const float4*)(qbase + (size_t)(q0 + r) * C3 + c4);
        Qs[r][c4 + 0] = v.x; Qs[r][c4 + 1] = v.y;
        Qs[r][c4 + 2] = v.z; Qs[r][c4 + 3] = v.w;
    }
    if (tid < BQ) { m_s[tid] = -1e30f; l_s[tid] = 0.0f; }

    float o[4][4];
#pragma unroll
    for (int i = 0; i < 4; i++)
#pragma unroll
        for (int j = 0; j < 4; j++) o[i][j] = 0.0f;
    __syncthreads();

    const int jend = q0 + BQ;  // keys strictly below this (causal)
    for (int j0 = 0; j0 < jend; j0 += BK) {
        // Load K,V tiles + padding mask
        for (int i = tid; i < BK * (DD / 4); i += 256) {
            int r = i >> 4, c4 = (i & 15) << 2;
            size_t off = (size_t)(j0 + r) * C3 + c4;
            float4 kv = *(const float4*)(kbase + off);
            float4 vv = *(const float4*)(vbase + off);
            Ks[r][c4 + 0] = kv.x; Ks[r][c4 + 1] = kv.y;
            Ks[r][c4 + 2] = kv.z; Ks[r][c4 + 3] = kv.w;
            Vs[r][c4 + 0] = vv.x; Vs[r][c4 + 1] = vv.y;
            Vs[r][c4 + 2] = vv.z; Vs[r][c4 + 3] = vv.w;
        }
        if (tid < BK) padv[tid] = padmask[b * TT + j0 + tid];
        __syncthreads();

        // S = Q @ K^T (4x2 per thread)
        float s[4][2];
#pragma unroll
        for (int i = 0; i < 4; i++) { s[i][0] = 0.0f; s[i][1] = 0.0f; }
#pragma unroll 8
        for (int d = 0; d < DD; d++) {
            float qv[4], kv[2];
#pragma unroll
            for (int ri = 0; ri < 4; ri++) qv[ri] = Qs[tr * 4 + ri][d];
            kv[0] = Ks[tc * 2 + 0][d];
            kv[1] = Ks[tc * 2 + 1][d];
#pragma unroll
            for (int ri = 0; ri < 4; ri++) {
                s[ri][0] = fmaf(qv[ri], kv[0], s[ri][0]);
                s[ri][1] = fmaf(qv[ri], kv[1], s[ri][1]);
            }
        }

        // Mask, stash raw scores, per-thread row max partials
#pragma unroll
        for (int ri = 0; ri < 4; ri++) {
            const int row = tr * 4 + ri;
            const int qi = q0 + row;
            float pm = -1e30f;
#pragma unroll
            for (int ci = 0; ci < 2; ci++) {
                const int col = tc * 2 + ci;
                const int kj = j0 + col;
                const bool valid = (kj <= qi) && (padv[col] != 0);
                float val = valid ? s[ri][ci] * scale : -1e30f;
                Ps[row][col] = val;
                pm = fmaxf(pm, val);
            }
            red[row][tc] = pm;
        }
        __syncthreads();

        // Row max + rescale factor (one thread per row)
        if (tid < BQ) {
            float mmax = m_s[tid];
#pragma unroll
            for (int t = 0; t < 16; t++) mmax = fmaxf(mmax, red[tid][t]);
            alpha_s[tid] = __expf(m_s[tid] - mmax);
            m_s[tid] = mmax;
        }
        __syncthreads();

        // Exponentiate, partial row sums, rescale O accumulators
#pragma unroll
        for (int ri = 0; ri < 4; ri++) {
            const int row = tr * 4 + ri;
            const float mrow = m_s[row];
            const float a = alpha_s[row];
            float ps = 0.0f;
#pragma unroll
            for (int ci = 0; ci < 2; ci++) {
                const int col = tc * 2 + ci;
                float p = __expf(Ps[row][col] - mrow);
                Ps[row][col] = p;
                ps += p;
            }
            red[row][tc] = ps;
#pragma unroll
            for (int ci = 0; ci < 4; ci++) o[ri][ci] *= a;
        }
        __syncthreads();

        if (tid < BQ) {
            float sum = 0.0f;
#pragma unroll
            for (int t = 0; t < 16; t++) sum += red[tid][t];
            l_s[tid] = l_s[tid] * alpha_s[tid] + sum;
        }

        // O += P @ V (4x4 per thread)
#pragma unroll 4
        for (int j = 0; j < BK; j++) {
            float pv[4], vv[4];
#pragma unroll
            for (int ri = 0; ri < 4; ri++) pv[ri] = Ps[tr * 4 + ri][j];
#pragma unroll
            for (int ci = 0; ci < 4; ci++) vv[ci] = Vs[j][tc * 4 + ci];
#pragma unroll
            for (int ri = 0; ri < 4; ri++)
#pragma unroll
                for (int ci = 0; ci < 4; ci++)
                    o[ri][ci] = fmaf(pv[ri], vv[ci], o[ri][ci]);
        }
        __syncthreads();  // protect smem (and l_s) for next tile / epilogue
    }

    // Epilogue: normalize and write y[b, q0+row, h*D + col]
#pragma unroll
    for (int ri = 0; ri < 4; ri++) {
        const int row = tr * 4 + ri;
        const float inv = 1.0f / l_s[row];
        float* yp = y + ((size_t)b * TT + q0 + row) * CC + h * DD + tc * 4;
        float4 v;
        v.x = o[ri][0] * inv; v.y = o[ri][1] * inv;
        v.z = o[ri][2] * inv; v.w = o[ri][3] * inv;
        *(float4*)yp = v;
    }
}

// ---------------------------------------------------------------------------
extern "C" void kernel_launch(void* const* d_in, const int* in_sizes, int n_in,
                              void* d_out, int out_size)
{
    const float* x      = (const float*)d_in[0];
    const float* W_kqv  = (const float*)d_in[1];
    const float* b_kqv  = (const float*)d_in[2];
    const float* W_proj = (const float*)d_in[3];
    const float* b_proj = (const float*)d_in[4];
    const int*   pad    = (const int*)d_in[5];
    float* out = (float*)d_out;

    float* kqv_ptr = nullptr;
    float* y_ptr = nullptr;
    cudaGetSymbolAddress((void**)&kqv_ptr, g_kqv);
    cudaGetSymbolAddress((void**)&y_ptr, g_y);

    const int M = BB * TT;  // 8192

    // 1) kqv = x @ W_kqv + b_kqv   [8192, 3072]
    {
        dim3 grid(C3 / 128, M / 128);
        sgemm_bias<<<grid, 256>>>(x, W_kqv, b_kqv, kqv_ptr, M, C3, CC);
    }
    // 2) flash attention -> y  [8192, 1024]
    {
        dim3 grid(TT / BQ, HH, BB);
        attn_kernel<<<grid, 256>>>(kqv_ptr, pad, y_ptr);
    }
    // 3) out = y @ W_proj + b_proj  [8192, 1024]
    {
        dim3 grid(CC / 128, M / 128);
        sgemm_bias<<<grid, 256>>>(y_ptr, W_proj, b_proj, out, M, CC, CC);
    }
}